// round 6
// baseline (speedup 1.0000x reference)
#include <cuda_runtime.h>
#include <cuda_fp16.h>
#include <cstdint>

#define DEPTH 4
#define B_    4096
#define H_    1024
#define K_    2048
#define N4H   4096

// ---------------- device scratch ----------------
__device__ __half g_A[DEPTH][B_][K_];    // [prev_out | s_h] fp16
__device__ __half g_W[DEPTH][K_][N4H];   // gate-interleaved: col 4j+g = orig g*1024+j

// ---------------- helpers ----------------
__device__ __forceinline__ uint32_t smem_u32(const void* p) {
    uint32_t a;
    asm("{ .reg .u64 t; cvta.to.shared.u64 t, %1; cvt.u32.u64 %0, t; }" : "=r"(a) : "l"(p));
    return a;
}
__device__ __forceinline__ void cp16(uint32_t dst, const void* src) {
    asm volatile("cp.async.cg.shared.global [%0], [%1], 16;"
                 :: "r"(dst), "l"(__cvta_generic_to_global(src)));
}
__device__ __forceinline__ void ldsm4(uint32_t* r, uint32_t addr) {
    asm volatile("ldmatrix.sync.aligned.m8n8.x4.shared.b16 {%0,%1,%2,%3}, [%4];"
                 : "=r"(r[0]), "=r"(r[1]), "=r"(r[2]), "=r"(r[3]) : "r"(addr));
}
__device__ __forceinline__ void ldsm4t(uint32_t* r, uint32_t addr) {
    asm volatile("ldmatrix.sync.aligned.m8n8.x4.trans.shared.b16 {%0,%1,%2,%3}, [%4];"
                 : "=r"(r[0]), "=r"(r[1]), "=r"(r[2]), "=r"(r[3]) : "r"(addr));
}
__device__ __forceinline__ void mma16816(float* c, const uint32_t* a, const uint32_t* b) {
    asm volatile("mma.sync.aligned.m16n8k16.row.col.f32.f16.f16.f32 "
                 "{%0,%1,%2,%3}, {%4,%5,%6,%7}, {%8,%9}, {%0,%1,%2,%3};"
                 : "+f"(c[0]), "+f"(c[1]), "+f"(c[2]), "+f"(c[3])
                 : "r"(a[0]), "r"(a[1]), "r"(a[2]), "r"(a[3]), "r"(b[0]), "r"(b[1]));
}
__device__ __forceinline__ float sigm(float x) { return 1.0f / (1.0f + __expf(-x)); }

// ---------------- conversion / packing ----------------
// W'[l][k][4j+g] = W[l][k][g*1024+j], fp16
__global__ void cvt_w(const float* __restrict__ W) {
    size_t i = (size_t)blockIdx.x * blockDim.x + threadIdx.x;   // (l,k,j)
    size_t l = i >> 21;                       // / (2048*1024)
    size_t rem = i & ((1u << 21) - 1);
    size_t k = rem >> 10, j = rem & 1023;
    const float* src = W + (l * K_ + k) * N4H;
    float vi = src[j], vf = src[1024 + j], vo = src[2048 + j], vg = src[3072 + j];
    __half2* dst = (__half2*)&g_W[l][k][4 * j];
    dst[0] = __floats2half2_rn(vi, vf);
    dst[1] = __floats2half2_rn(vo, vg);
}
__global__ void pack_sh(const float* __restrict__ sh) {
    size_t i = (size_t)blockIdx.x * blockDim.x + threadIdx.x;
    size_t e = i * 4;
    size_t l = e / ((size_t)B_ * H_);
    size_t r = e % ((size_t)B_ * H_);
    size_t m = r >> 10, j = r & 1023;
    float4 v = ((const float4*)sh)[i];
    __half2* dst = (__half2*)&g_A[l][m][H_ + j];
    dst[0] = __floats2half2_rn(v.x, v.y);
    dst[1] = __floats2half2_rn(v.z, v.w);
}
__global__ void pack_x(const float* __restrict__ x) {
    size_t i = (size_t)blockIdx.x * blockDim.x + threadIdx.x;
    size_t e = i * 4;
    size_t m = e >> 10, j = e & 1023;
    float4 v = ((const float4*)x)[i];
    __half2* dst = (__half2*)&g_A[0][m][j];
    dst[0] = __floats2half2_rn(v.x, v.y);
    dst[1] = __floats2half2_rn(v.z, v.w);
}

// ---------------- fused GEMM + LSTM ----------------
// BM=128, BN=128 (= 32 gate-quads), BK=64, 3 stages, 1 sync/iter,
// 256 thr (8 warps = 2m x 4n), warp tile 64x32, 2 CTAs/SM.
#define BK      64
#define ASTRIDE 144                // bytes per A smem row (128 data + 16 pad), 144/16=9 odd
#define BSTRIDE 272                // bytes per B smem row (256 data + 16 pad), 17 odd
#define A_STG   (128 * ASTRIDE)    // 18432
#define B_STG   (BK * BSTRIDE)     // 17408
#define STG     (A_STG + B_STG)    // 35840
#define NSTAGE  3
#define SMEM_G  (NSTAGE * STG)     // 107520

__global__ void __launch_bounds__(256, 2)
lstm_gemm(int layer, const float* __restrict__ bias, const float* __restrict__ c_in,
          float* __restrict__ h_out, float* __restrict__ c_out,
          float* __restrict__ final_out) {
    extern __shared__ __align__(16) char smem[];
    const uint32_t sbase = smem_u32(smem);

    const int tid = threadIdx.x;
    const int wid = tid >> 5, lane = tid & 31;
    const int m0 = blockIdx.y * 128, n0 = blockIdx.x * 128;
    const int wm = (wid >> 2) * 64, wn = (wid & 3) * 32;

    const __half* Ag = &g_A[layer][0][0];
    const __half* Wg = &g_W[layer][0][0];
    __half* a_next = (layer + 1 < DEPTH) ? &g_A[layer + 1][0][0] : nullptr;

    // load coords: A 128 rows x 8 chunks (4/thread); B 64 rows x 16 chunks (4/thread)
    const int ar = tid >> 1, ac = (tid & 1) * 4;
    const int br = tid >> 2, bc = (tid & 3) * 4;

    auto load_stage = [&](int s, int k0) {
        uint32_t da = sbase + s * STG;
        uint32_t db = da + A_STG;
        #pragma unroll
        for (int q = 0; q < 4; ++q)
            cp16(da + ar * ASTRIDE + (ac + q) * 16,
                 Ag + (size_t)(m0 + ar) * K_ + k0 + (ac + q) * 8);
        #pragma unroll
        for (int q = 0; q < 4; ++q)
            cp16(db + br * BSTRIDE + (bc + q) * 16,
                 Wg + (size_t)(k0 + br) * N4H + n0 + (bc + q) * 8);
        asm volatile("cp.async.commit_group;" ::: "memory");
    };

    float acc[4][4][4];
    #pragma unroll
    for (int i = 0; i < 4; ++i)
        #pragma unroll
        for (int j = 0; j < 4; ++j)
            #pragma unroll
            for (int q = 0; q < 4; ++q) acc[i][j][q] = 0.f;

    load_stage(0, 0);
    load_stage(1, BK);

    const int NIT = K_ / BK;  // 32
    for (int kt = 0; kt < NIT; ++kt) {
        if (kt + 1 < NIT) asm volatile("cp.async.wait_group 1;" ::: "memory");
        else              asm volatile("cp.async.wait_group 0;" ::: "memory");
        __syncthreads();

        if (kt + 2 < NIT) load_stage((kt + 2) % NSTAGE, (kt + 2) * BK);

        const uint32_t da = sbase + (kt % NSTAGE) * STG;
        const uint32_t db = da + A_STG;
        #pragma unroll
        for (int k16 = 0; k16 < 4; ++k16) {
            uint32_t af[4][4], bf[2][4];
            #pragma unroll
            for (int mf = 0; mf < 4; ++mf)
                ldsm4(af[mf], da + (wm + mf * 16 + (lane & 15)) * ASTRIDE
                                 + k16 * 32 + (lane >> 4) * 16);
            #pragma unroll
            for (int ns = 0; ns < 2; ++ns)
                ldsm4t(bf[ns], db + (k16 * 16 + (lane & 15)) * BSTRIDE
                                  + (wn + ns * 16 + (lane >> 4) * 8) * 2);
            #pragma unroll
            for (int mf = 0; mf < 4; ++mf)
                #pragma unroll
                for (int nf = 0; nf < 4; ++nf)
                    mma16816(acc[mf][nf], af[mf], &bf[nf >> 1][(nf & 1) * 2]);
        }
    }

    // -------- fused LSTM epilogue (gate-interleaved columns) --------
    // acc tile (mf,nf): rows r=lane>>2 (+8), cols c0=(lane&3)*2. Permuted layout:
    // q=lane&3: q=0 -> {i,f} of j0 ; q=1 -> {o,g} of j0 ; q=2 -> {i,f} of j0+1 ; q=3 -> {o,g} of j0+1
    const int q = lane & 3;
    const bool has_if = (q & 1) == 0;   // holds {i,f}; partner (lane^1) holds {o,g}
    const int rbase = m0 + wm + (lane >> 2);

    // hoist bias per nf (j depends on nf and q only)
    float bi[4], bfs[4], bo[4], bg[4];
    int jcol[4];
    #pragma unroll
    for (int nf = 0; nf < 4; ++nf) {
        int j = (n0 + wn + nf * 8) / 4 + (q >> 1);
        jcol[nf] = j;
        bi[nf]  = bias[j];
        bfs[nf] = bias[1024 + j];
        bo[nf]  = bias[2048 + j];
        bg[nf]  = bias[3072 + j];
    }

    #pragma unroll
    for (int mf = 0; mf < 4; ++mf) {
        #pragma unroll
        for (int nf = 0; nf < 4; ++nf) {
            float v0 = acc[mf][nf][0], v1 = acc[mf][nf][1];
            float v2 = acc[mf][nf][2], v3 = acc[mf][nf][3];
            float p0 = __shfl_xor_sync(0xffffffffu, v0, 1);
            float p1 = __shfl_xor_sync(0xffffffffu, v1, 1);
            float p2 = __shfl_xor_sync(0xffffffffu, v2, 1);
            float p3 = __shfl_xor_sync(0xffffffffu, v3, 1);
            // q even -> compute row r (use v0,v1 as i,f ; p0,p1 as o,g)
            // q odd  -> compute row r+8 (use p2,p3 as i,f ; v2,v3 as o,g)
            float zi, zf, zo, zg;
            int m;
            if (has_if) { zi = v0; zf = v1; zo = p0; zg = p1; m = rbase + mf * 16; }
            else        { zi = p2; zf = p3; zo = v2; zg = v3; m = rbase + mf * 16 + 8; }
            const int j = jcol[nf];
            float ig = sigm(zi + bi[nf]);
            float fg = sigm(zf + bfs[nf]);
            float og = sigm(zo + bo[nf]);
            float gg = tanhf(zg + bg[nf]);
            float cn = c_in[(size_t)m * H_ + j] * fg + gg * ig;
            float hn = tanhf(cn) * og;
            const size_t off = (size_t)m * H_ + j;
            h_out[off] = hn;
            c_out[off] = cn;
            if (a_next) a_next[(size_t)m * K_ + j] = __float2half(hn);
            if (final_out) final_out[off] = hn;
        }
    }
}

// ---------------- launch ----------------
extern "C" void kernel_launch(void* const* d_in, const int* in_sizes, int n_in,
                              void* d_out, int out_size) {
    const float* x  = (const float*)d_in[0];
    const float* sh = (const float*)d_in[1];
    const float* sc = (const float*)d_in[2];
    const float* W  = (const float*)d_in[3];
    const float* b  = (const float*)d_in[4];
    float* out = (float*)d_out;

    const size_t BH = (size_t)B_ * H_;
    float* out_final = out;
    float* out_h     = out + BH;
    float* out_c     = out + BH + DEPTH * BH;

    cudaFuncSetAttribute(lstm_gemm, cudaFuncAttributeMaxDynamicSharedMemorySize, SMEM_G);

    cvt_w<<<(DEPTH * (size_t)K_ * 1024) / 256, 256>>>(W);
    pack_sh<<<(DEPTH * BH / 4) / 256, 256>>>(sh);
    pack_x<<<(BH / 4) / 256, 256>>>(x);

    for (int l = 0; l < DEPTH; ++l) {
        lstm_gemm<<<dim3(N4H / 128, B_ / 128), 256, SMEM_G>>>(
            l, b + (size_t)l * N4H, sc + (size_t)l * BH,
            out_h + (size_t)l * BH, out_c + (size_t)l * BH,
            (l == DEPTH - 1) ? out_final : nullptr);
    }
}

// round 8
// speedup vs baseline: 1.2999x; 1.2999x over previous
#include <cuda_runtime.h>
#include <cuda_fp16.h>
#include <cstdint>

#define DEPTH 4
#define B_    4096
#define H_    1024
#define K_    2048
#define N4H   4096

// ---------------- device scratch ----------------
__device__ __half g_A[DEPTH][B_][K_];    // [prev_out | s_h] fp16
__device__ __half g_W[DEPTH][K_][N4H];   // gate-interleaved: col 4j+g = orig g*1024+j

// ---------------- helpers ----------------
__device__ __forceinline__ uint32_t smem_u32(const void* p) {
    uint32_t a;
    asm("{ .reg .u64 t; cvta.to.shared.u64 t, %1; cvt.u32.u64 %0, t; }" : "=r"(a) : "l"(p));
    return a;
}
__device__ __forceinline__ void cp16(uint32_t dst, const void* src) {
    asm volatile("cp.async.cg.shared.global [%0], [%1], 16;"
                 :: "r"(dst), "l"(__cvta_generic_to_global(src)));
}
__device__ __forceinline__ void ldsm4(uint32_t* r, uint32_t addr) {
    asm volatile("ldmatrix.sync.aligned.m8n8.x4.shared.b16 {%0,%1,%2,%3}, [%4];"
                 : "=r"(r[0]), "=r"(r[1]), "=r"(r[2]), "=r"(r[3]) : "r"(addr));
}
__device__ __forceinline__ void ldsm4t(uint32_t* r, uint32_t addr) {
    asm volatile("ldmatrix.sync.aligned.m8n8.x4.trans.shared.b16 {%0,%1,%2,%3}, [%4];"
                 : "=r"(r[0]), "=r"(r[1]), "=r"(r[2]), "=r"(r[3]) : "r"(addr));
}
__device__ __forceinline__ void mma16816(float* c, const uint32_t* a, const uint32_t* b) {
    asm volatile("mma.sync.aligned.m16n8k16.row.col.f32.f16.f16.f32 "
                 "{%0,%1,%2,%3}, {%4,%5,%6,%7}, {%8,%9}, {%0,%1,%2,%3};"
                 : "+f"(c[0]), "+f"(c[1]), "+f"(c[2]), "+f"(c[3])
                 : "r"(a[0]), "r"(a[1]), "r"(a[2]), "r"(a[3]), "r"(b[0]), "r"(b[1]));
}
__device__ __forceinline__ float sigm(float x) { return 1.0f / (1.0f + __expf(-x)); }

// ---------------- conversion / packing ----------------
// W'[l][k][4j+g] = W[l][k][g*1024+j], fp16  (verified in R6: identical rel_err)
__global__ void cvt_w(const float* __restrict__ W) {
    size_t i = (size_t)blockIdx.x * blockDim.x + threadIdx.x;   // (l,k,j)
    size_t l = i >> 21;
    size_t rem = i & ((1u << 21) - 1);
    size_t k = rem >> 10, j = rem & 1023;
    const float* src = W + (l * K_ + k) * N4H;
    float vi = src[j], vf = src[1024 + j], vo = src[2048 + j], vg = src[3072 + j];
    __half2* dst = (__half2*)&g_W[l][k][4 * j];
    dst[0] = __floats2half2_rn(vi, vf);
    dst[1] = __floats2half2_rn(vo, vg);
}
__global__ void pack_sh(const float* __restrict__ sh) {
    size_t i = (size_t)blockIdx.x * blockDim.x + threadIdx.x;
    size_t e = i * 4;
    size_t l = e / ((size_t)B_ * H_);
    size_t r = e % ((size_t)B_ * H_);
    size_t m = r >> 10, j = r & 1023;
    float4 v = ((const float4*)sh)[i];
    __half2* dst = (__half2*)&g_A[l][m][H_ + j];
    dst[0] = __floats2half2_rn(v.x, v.y);
    dst[1] = __floats2half2_rn(v.z, v.w);
}
__global__ void pack_x(const float* __restrict__ x) {
    size_t i = (size_t)blockIdx.x * blockDim.x + threadIdx.x;
    size_t e = i * 4;
    size_t m = e >> 10, j = e & 1023;
    float4 v = ((const float4*)x)[i];
    __half2* dst = (__half2*)&g_A[0][m][j];
    dst[0] = __floats2half2_rn(v.x, v.y);
    dst[1] = __floats2half2_rn(v.z, v.w);
}

// ---------------- fused GEMM + LSTM (staged epilogue) ----------------
// BM=128, BN=128 (=32 gate-quads), BK=32, 4 stages, 1 sync/iter,
// 256 thr (8 warps = 2m x 4n), warp tile 64x32, 2 CTAs/SM.
#define BK      32
#define ASTRIDE 80                 // A smem row bytes (64 data + 16 pad)
#define BSTRIDE 272                // B smem row bytes (256 data + 16 pad)
#define A_STG   (128 * ASTRIDE)    // 10240
#define B_STG   (BK * BSTRIDE)     // 8704
#define STG     (A_STG + B_STG)    // 18944
#define NSTAGE  4
#define CIN_STRIDE 144             // c_in tile row bytes (128 data + 16 pad)
#define CIN_BYTES  (128 * CIN_STRIDE)          // 18432
#define SMEM_G  (NSTAGE * STG + CIN_BYTES)     // 94208

__global__ void __launch_bounds__(256, 2)
lstm_gemm(int layer, const float* __restrict__ bias, const float* __restrict__ c_in,
          float* __restrict__ h_out, float* __restrict__ c_out,
          float* __restrict__ final_out) {
    extern __shared__ __align__(16) char smem[];
    const uint32_t sbase = smem_u32(smem);
    const uint32_t scin  = sbase + NSTAGE * STG;

    const int tid = threadIdx.x;
    const int wid = tid >> 5, lane = tid & 31;
    const int m0 = blockIdx.y * 128, n0 = blockIdx.x * 128;
    const int jbase = n0 >> 2;                     // 32 j-cols per CTA
    const int wm = (wid >> 2) * 64, wn = (wid & 3) * 32;

    const __half* Ag = &g_A[layer][0][0];
    const __half* Wg = &g_W[layer][0][0];
    __half* a_next = (layer + 1 < DEPTH) ? &g_A[layer + 1][0][0] : nullptr;

    const int ar = tid >> 1, ac = (tid & 1) * 2;
    const int br = tid >> 4, bc = tid & 15;

    auto load_stage = [&](int s, int k0) {
        uint32_t da = sbase + s * STG;
        uint32_t db = da + A_STG;
        cp16(da + ar * ASTRIDE + ac * 16,       Ag + (size_t)(m0 + ar) * K_ + k0 + ac * 8);
        cp16(da + ar * ASTRIDE + (ac + 1) * 16, Ag + (size_t)(m0 + ar) * K_ + k0 + (ac + 1) * 8);
        cp16(db + br * BSTRIDE + bc * 16,        Wg + (size_t)(k0 + br) * N4H + n0 + bc * 8);
        cp16(db + (br + 16) * BSTRIDE + bc * 16, Wg + (size_t)(k0 + br + 16) * N4H + n0 + bc * 8);
        asm volatile("cp.async.commit_group;" ::: "memory");
    };

    // c_in tile prefetch: own (oldest) group, retires before first stage wait
    #pragma unroll
    for (int it = 0; it < 4; ++it) {
        int idx = tid + 256 * it;       // 0..1023
        int r = idx >> 3, ch = idx & 7;
        cp16(scin + r * CIN_STRIDE + ch * 16,
             c_in + (size_t)(m0 + r) * H_ + jbase + ch * 4);
    }
    asm volatile("cp.async.commit_group;" ::: "memory");

    float acc[4][4][4];
    #pragma unroll
    for (int i = 0; i < 4; ++i)
        #pragma unroll
        for (int j = 0; j < 4; ++j)
            #pragma unroll
            for (int q = 0; q < 4; ++q) acc[i][j][q] = 0.f;

    load_stage(0, 0);
    load_stage(1, BK);
    load_stage(2, 2 * BK);

    const int NIT = K_ / BK;  // 64
    for (int kt = 0; kt < NIT; ++kt) {
        if (kt + 3 <= NIT - 1)      asm volatile("cp.async.wait_group 2;" ::: "memory");
        else if (kt + 2 <= NIT - 1) asm volatile("cp.async.wait_group 1;" ::: "memory");
        else                        asm volatile("cp.async.wait_group 0;" ::: "memory");
        __syncthreads();

        if (kt + 3 < NIT) load_stage((kt + 3) % NSTAGE, (kt + 3) * BK);

        const uint32_t da = sbase + (kt % NSTAGE) * STG;
        const uint32_t db = da + A_STG;
        #pragma unroll
        for (int k16 = 0; k16 < 2; ++k16) {
            uint32_t af[4][4], bf[2][4];
            #pragma unroll
            for (int mf = 0; mf < 4; ++mf)
                ldsm4(af[mf], da + (wm + mf * 16 + (lane & 15)) * ASTRIDE
                                 + k16 * 32 + (lane >> 4) * 16);
            #pragma unroll
            for (int ns = 0; ns < 2; ++ns)
                ldsm4t(bf[ns], db + (k16 * 16 + (lane & 15)) * BSTRIDE
                                  + (wn + ns * 16 + (lane >> 4) * 8) * 2);
            #pragma unroll
            for (int mf = 0; mf < 4; ++mf)
                #pragma unroll
                for (int nf = 0; nf < 4; ++nf)
                    mma16816(acc[mf][nf], af[mf], &bf[nf >> 1][(nf & 1) * 2]);
        }
    }
    __syncthreads();   // pipeline smem free; reuse for h/c staging

    // -------- LSTM epilogue: compute into smem (mapping verified in R6) --------
    float* sh_h = (float*)smem;                     // [128][33]
    float* sh_c = sh_h + 128 * 33;                  // [128][33]
    const float* sh_cin = (const float*)(smem + (NSTAGE * STG));  // [128][36] (stride 144B)

    const int q = lane & 3;
    const bool has_if = (q & 1) == 0;
    const int rloc = wm + (lane >> 2);

    float bi[4], bfs[4], bo[4], bg[4];
    int jloc[4];
    #pragma unroll
    for (int nf = 0; nf < 4; ++nf) {
        int jl = (wn >> 2) + nf * 2 + (q >> 1);     // 0..31
        jloc[nf] = jl;
        int j = jbase + jl;
        bi[nf]  = bias[j];
        bfs[nf] = bias[1024 + j];
        bo[nf]  = bias[2048 + j];
        bg[nf]  = bias[3072 + j];
    }

    #pragma unroll
    for (int mf = 0; mf < 4; ++mf) {
        #pragma unroll
        for (int nf = 0; nf < 4; ++nf) {
            float v0 = acc[mf][nf][0], v1 = acc[mf][nf][1];
            float v2 = acc[mf][nf][2], v3 = acc[mf][nf][3];
            float p0 = __shfl_xor_sync(0xffffffffu, v0, 1);
            float p1 = __shfl_xor_sync(0xffffffffu, v1, 1);
            float p2 = __shfl_xor_sync(0xffffffffu, v2, 1);
            float p3 = __shfl_xor_sync(0xffffffffu, v3, 1);
            float zi, zf, zo, zg;
            int ml;
            if (has_if) { zi = v0; zf = v1; zo = p0; zg = p1; ml = rloc + mf * 16; }
            else        { zi = p2; zf = p3; zo = v2; zg = v3; ml = rloc + mf * 16 + 8; }
            const int jl = jloc[nf];
            float ig = sigm(zi + bi[nf]);
            float fg = sigm(zf + bfs[nf]);
            float og = sigm(zo + bo[nf]);
            float gg = tanhf(zg + bg[nf]);
            float cn = sh_cin[ml * 36 + jl] * fg + gg * ig;
            float hn = tanhf(cn) * og;
            sh_h[ml * 33 + jl] = hn;
            sh_c[ml * 33 + jl] = cn;
        }
    }
    __syncthreads();

    // -------- coalesced output pass: 128 rows x 32 cols --------
    #pragma unroll
    for (int it = 0; it < 16; ++it) {
        int idx = tid + 256 * it;        // 0..4095
        int r = idx >> 5, c2 = idx & 31;
        float hv = sh_h[r * 33 + c2];
        float cv = sh_c[r * 33 + c2];
        const size_t off = (size_t)(m0 + r) * H_ + jbase + c2;
        h_out[off] = hv;
        c_out[off] = cv;
        if (final_out) final_out[off] = hv;
        if (a_next) a_next[(size_t)(m0 + r) * K_ + jbase + c2] = __float2half(hv);
    }
}

// ---------------- launch ----------------
extern "C" void kernel_launch(void* const* d_in, const int* in_sizes, int n_in,
                              void* d_out, int out_size) {
    const float* x  = (const float*)d_in[0];
    const float* sh = (const float*)d_in[1];
    const float* sc = (const float*)d_in[2];
    const float* W  = (const float*)d_in[3];
    const float* b  = (const float*)d_in[4];
    float* out = (float*)d_out;

    const size_t BH = (size_t)B_ * H_;
    float* out_final = out;
    float* out_h     = out + BH;
    float* out_c     = out + BH + DEPTH * BH;

    cudaFuncSetAttribute(lstm_gemm, cudaFuncAttributeMaxDynamicSharedMemorySize, SMEM_G);

    cvt_w<<<(DEPTH * (size_t)K_ * 1024) / 256, 256>>>(W);
    pack_sh<<<(DEPTH * BH / 4) / 256, 256>>>(sh);
    pack_x<<<(BH / 4) / 256, 256>>>(x);

    for (int l = 0; l < DEPTH; ++l) {
        lstm_gemm<<<dim3(N4H / 128, B_ / 128), 256, SMEM_G>>>(
            l, b + (size_t)l * N4H, sc + (size_t)l * BH,
            out_h + (size_t)l * BH, out_c + (size_t)l * BH,
            (l == DEPTH - 1) ? out_final : nullptr);
    }
}

// round 9
// speedup vs baseline: 1.4515x; 1.1166x over previous
#include <cuda_runtime.h>
#include <cuda_fp16.h>
#include <cstdint>

#define DEPTH 4
#define B_    4096
#define H_    1024
#define K_    2048
#define N4H   4096

// ---------------- device scratch ----------------
__device__ __half g_A[DEPTH][B_][K_];    // [prev_out | s_h] fp16
__device__ __half g_W[DEPTH][K_][N4H];   // gate-interleaved: col 4j+g = orig g*1024+j

// ---------------- helpers ----------------
__device__ __forceinline__ uint32_t smem_u32(const void* p) {
    uint32_t a;
    asm("{ .reg .u64 t; cvta.to.shared.u64 t, %1; cvt.u32.u64 %0, t; }" : "=r"(a) : "l"(p));
    return a;
}
__device__ __forceinline__ void cp16(uint32_t dst, const void* src) {
    asm volatile("cp.async.cg.shared.global [%0], [%1], 16;"
                 :: "r"(dst), "l"(__cvta_generic_to_global(src)));
}
__device__ __forceinline__ void ldsm4(uint32_t* r, uint32_t addr) {
    asm volatile("ldmatrix.sync.aligned.m8n8.x4.shared.b16 {%0,%1,%2,%3}, [%4];"
                 : "=r"(r[0]), "=r"(r[1]), "=r"(r[2]), "=r"(r[3]) : "r"(addr));
}
__device__ __forceinline__ void ldsm4t(uint32_t* r, uint32_t addr) {
    asm volatile("ldmatrix.sync.aligned.m8n8.x4.trans.shared.b16 {%0,%1,%2,%3}, [%4];"
                 : "=r"(r[0]), "=r"(r[1]), "=r"(r[2]), "=r"(r[3]) : "r"(addr));
}
__device__ __forceinline__ void mma16816(float* c, const uint32_t* a, const uint32_t* b) {
    asm volatile("mma.sync.aligned.m16n8k16.row.col.f32.f16.f16.f32 "
                 "{%0,%1,%2,%3}, {%4,%5,%6,%7}, {%8,%9}, {%0,%1,%2,%3};"
                 : "+f"(c[0]), "+f"(c[1]), "+f"(c[2]), "+f"(c[3])
                 : "r"(a[0]), "r"(a[1]), "r"(a[2]), "r"(a[3]), "r"(b[0]), "r"(b[1]));
}
__device__ __forceinline__ float sigm(float x) { return 1.0f / (1.0f + __expf(-x)); }

// ---------------- conversion / packing ----------------
// W'[l][k][4j+g] = W[l][k][g*1024+j], fp16  (mapping verified: rel_err identical)
__global__ void cvt_w(const float* __restrict__ W) {
    size_t i = (size_t)blockIdx.x * blockDim.x + threadIdx.x;   // (l,k,j)
    size_t l = i >> 21;
    size_t rem = i & ((1u << 21) - 1);
    size_t k = rem >> 10, j = rem & 1023;
    const float* src = W + (l * K_ + k) * N4H;
    float vi = src[j], vf = src[1024 + j], vo = src[2048 + j], vg = src[3072 + j];
    __half2* dst = (__half2*)&g_W[l][k][4 * j];
    dst[0] = __floats2half2_rn(vi, vf);
    dst[1] = __floats2half2_rn(vo, vg);
}
__global__ void pack_sh(const float* __restrict__ sh) {
    size_t i = (size_t)blockIdx.x * blockDim.x + threadIdx.x;
    size_t e = i * 4;
    size_t l = e / ((size_t)B_ * H_);
    size_t r = e % ((size_t)B_ * H_);
    size_t m = r >> 10, j = r & 1023;
    float4 v = ((const float4*)sh)[i];
    __half2* dst = (__half2*)&g_A[l][m][H_ + j];
    dst[0] = __floats2half2_rn(v.x, v.y);
    dst[1] = __floats2half2_rn(v.z, v.w);
}
__global__ void pack_x(const float* __restrict__ x) {
    size_t i = (size_t)blockIdx.x * blockDim.x + threadIdx.x;
    size_t e = i * 4;
    size_t m = e >> 10, j = e & 1023;
    float4 v = ((const float4*)x)[i];
    __half2* dst = (__half2*)&g_A[0][m][j];
    dst[0] = __floats2half2_rn(v.x, v.y);
    dst[1] = __floats2half2_rn(v.z, v.w);
}

// ---------------- fused GEMM + LSTM ----------------
// BM=128, BN=128, BK=32, 5 stages, 1 sync per 2 iters, 256 thr (8 warps 2m x 4n),
// warp tile 64x32, 2 CTAs/SM.
#define BK      32
#define ASTRIDE 80
#define BSTRIDE 272
#define A_STG   (128 * ASTRIDE)    // 10240
#define B_STG   (BK * BSTRIDE)     // 8704
#define STG     (A_STG + B_STG)    // 18944
#define NSTAGE  5
#define CIN_STRIDE 144
#define CIN_BYTES  (128 * CIN_STRIDE)          // 18432
#define SMEM_G  (NSTAGE * STG + CIN_BYTES)     // 113152

__global__ void __launch_bounds__(256, 2)
lstm_gemm(int layer, const float* __restrict__ bias, const float* __restrict__ c_in,
          float* __restrict__ h_out, float* __restrict__ c_out,
          float* __restrict__ final_out) {
    extern __shared__ __align__(16) char smem[];
    const uint32_t sbase = smem_u32(smem);
    const uint32_t scin  = sbase + NSTAGE * STG;

    const int tid = threadIdx.x;
    const int wid = tid >> 5, lane = tid & 31;
    const int m0 = blockIdx.y * 128, n0 = blockIdx.x * 128;
    const int jbase = n0 >> 2;
    const int wm = (wid >> 2) * 64, wn = (wid & 3) * 32;

    const __half* Ag = &g_A[layer][0][0];
    const __half* Wg = &g_W[layer][0][0];
    __half* a_next = (layer + 1 < DEPTH) ? &g_A[layer + 1][0][0] : nullptr;

    const int ar = tid >> 1, ac = (tid & 1) * 2;
    const int br = tid >> 4, bc = tid & 15;

    auto load_stage = [&](int s, int k0) {
        uint32_t da = sbase + s * STG;
        uint32_t db = da + A_STG;
        cp16(da + ar * ASTRIDE + ac * 16,       Ag + (size_t)(m0 + ar) * K_ + k0 + ac * 8);
        cp16(da + ar * ASTRIDE + (ac + 1) * 16, Ag + (size_t)(m0 + ar) * K_ + k0 + (ac + 1) * 8);
        cp16(db + br * BSTRIDE + bc * 16,        Wg + (size_t)(k0 + br) * N4H + n0 + bc * 8);
        cp16(db + (br + 16) * BSTRIDE + bc * 16, Wg + (size_t)(k0 + br + 16) * N4H + n0 + bc * 8);
        asm volatile("cp.async.commit_group;" ::: "memory");
    };

    float acc[4][4][4];
    #pragma unroll
    for (int i = 0; i < 4; ++i)
        #pragma unroll
        for (int j = 0; j < 4; ++j)
            #pragma unroll
            for (int q = 0; q < 4; ++q) acc[i][j][q] = 0.f;

    // c_in prefetch: oldest group, retired by the first wait below
    #pragma unroll
    for (int it = 0; it < 4; ++it) {
        int idx = tid + 256 * it;
        int r = idx >> 3, ch = idx & 7;
        cp16(scin + r * CIN_STRIDE + ch * 16,
             c_in + (size_t)(m0 + r) * H_ + jbase + ch * 4);
    }
    asm volatile("cp.async.commit_group;" ::: "memory");

    load_stage(0, 0);
    load_stage(1, BK);
    load_stage(2, 2 * BK);

    // one sub-iteration: fragments+MMA for stage `st`, with optional interleaved prefetch
    auto subiter = [&](int st, int pf_slot, int pf_k0, bool do_pf) {
        const uint32_t da = sbase + st * STG;
        const uint32_t db = da + A_STG;
        uint32_t af[4][4], bf[2][4];
        // k16 = 0 fragments
        #pragma unroll
        for (int mf = 0; mf < 4; ++mf)
            ldsm4(af[mf], da + (wm + mf * 16 + (lane & 15)) * ASTRIDE + (lane >> 4) * 16);
        #pragma unroll
        for (int ns = 0; ns < 2; ++ns)
            ldsm4t(bf[ns], db + (lane & 15) * BSTRIDE
                              + (wn + ns * 16 + (lane >> 4) * 8) * 2);
        if (do_pf) load_stage(pf_slot, pf_k0);
        #pragma unroll
        for (int mf = 0; mf < 4; ++mf)
            #pragma unroll
            for (int nf = 0; nf < 4; ++nf)
                mma16816(acc[mf][nf], af[mf], &bf[nf >> 1][(nf & 1) * 2]);
        // k16 = 1 fragments
        #pragma unroll
        for (int mf = 0; mf < 4; ++mf)
            ldsm4(af[mf], da + (wm + mf * 16 + (lane & 15)) * ASTRIDE + 32 + (lane >> 4) * 16);
        #pragma unroll
        for (int ns = 0; ns < 2; ++ns)
            ldsm4t(bf[ns], db + (16 + (lane & 15)) * BSTRIDE
                              + (wn + ns * 16 + (lane >> 4) * 8) * 2);
        #pragma unroll
        for (int mf = 0; mf < 4; ++mf)
            #pragma unroll
            for (int nf = 0; nf < 4; ++nf)
                mma16816(acc[mf][nf], af[mf], &bf[nf >> 1][(nf & 1) * 2]);
    };

    const int NIT = K_ / BK;  // 64
    #pragma unroll 1
    for (int kt = 0; kt < NIT; kt += 2) {
        if (kt + 2 < NIT) asm volatile("cp.async.wait_group 1;" ::: "memory");
        else              asm volatile("cp.async.wait_group 0;" ::: "memory");
        __syncthreads();
        subiter(kt % NSTAGE,       (kt + 3) % NSTAGE, (kt + 3) * BK, kt + 3 < NIT);
        subiter((kt + 1) % NSTAGE, (kt + 4) % NSTAGE, (kt + 4) * BK, kt + 4 < NIT);
    }
    __syncthreads();   // pipeline smem free; reuse for h/c staging

    // -------- LSTM epilogue (mapping verified) --------
    float* sh_h = (float*)smem;                     // [128][33]
    float* sh_c = sh_h + 128 * 33;                  // [128][33]
    const float* sh_cin = (const float*)(smem + (NSTAGE * STG));

    const int q = lane & 3;
    const bool has_if = (q & 1) == 0;
    const int rloc = wm + (lane >> 2);

    float bi[4], bfs[4], bo[4], bg[4];
    int jloc[4];
    #pragma unroll
    for (int nf = 0; nf < 4; ++nf) {
        int jl = (wn >> 2) + nf * 2 + (q >> 1);
        jloc[nf] = jl;
        int j = jbase + jl;
        bi[nf]  = bias[j];
        bfs[nf] = bias[1024 + j];
        bo[nf]  = bias[2048 + j];
        bg[nf]  = bias[3072 + j];
    }

    #pragma unroll
    for (int mf = 0; mf < 4; ++mf) {
        #pragma unroll
        for (int nf = 0; nf < 4; ++nf) {
            float v0 = acc[mf][nf][0], v1 = acc[mf][nf][1];
            float v2 = acc[mf][nf][2], v3 = acc[mf][nf][3];
            float p0 = __shfl_xor_sync(0xffffffffu, v0, 1);
            float p1 = __shfl_xor_sync(0xffffffffu, v1, 1);
            float p2 = __shfl_xor_sync(0xffffffffu, v2, 1);
            float p3 = __shfl_xor_sync(0xffffffffu, v3, 1);
            float zi, zf, zo, zg;
            int ml;
            if (has_if) { zi = v0; zf = v1; zo = p0; zg = p1; ml = rloc + mf * 16; }
            else        { zi = p2; zf = p3; zo = v2; zg = v3; ml = rloc + mf * 16 + 8; }
            const int jl = jloc[nf];
            float ig = sigm(zi + bi[nf]);
            float fg = sigm(zf + bfs[nf]);
            float og = sigm(zo + bo[nf]);
            float gg = tanhf(zg + bg[nf]);
            float cn = sh_cin[ml * 36 + jl] * fg + gg * ig;
            float hn = tanhf(cn) * og;
            sh_h[ml * 33 + jl] = hn;
            sh_c[ml * 33 + jl] = cn;
        }
    }
    __syncthreads();

    // -------- coalesced output pass --------
    #pragma unroll
    for (int it = 0; it < 16; ++it) {
        int idx = tid + 256 * it;
        int r = idx >> 5, c2 = idx & 31;
        float hv = sh_h[r * 33 + c2];
        float cv = sh_c[r * 33 + c2];
        const size_t off = (size_t)(m0 + r) * H_ + jbase + c2;
        h_out[off] = hv;
        c_out[off] = cv;
        if (final_out) final_out[off] = hv;
        if (a_next) a_next[(size_t)(m0 + r) * K_ + jbase + c2] = __float2half(hv);
    }
}

// ---------------- launch ----------------
extern "C" void kernel_launch(void* const* d_in, const int* in_sizes, int n_in,
                              void* d_out, int out_size) {
    const float* x  = (const float*)d_in[0];
    const float* sh = (const float*)d_in[1];
    const float* sc = (const float*)d_in[2];
    const float* W  = (const float*)d_in[3];
    const float* b  = (const float*)d_in[4];
    float* out = (float*)d_out;

    const size_t BH = (size_t)B_ * H_;
    float* out_final = out;
    float* out_h     = out + BH;
    float* out_c     = out + BH + DEPTH * BH;

    cudaFuncSetAttribute(lstm_gemm, cudaFuncAttributeMaxDynamicSharedMemorySize, SMEM_G);

    cvt_w<<<(DEPTH * (size_t)K_ * 1024) / 256, 256>>>(W);
    pack_sh<<<(DEPTH * BH / 4) / 256, 256>>>(sh);
    pack_x<<<(BH / 4) / 256, 256>>>(x);

    for (int l = 0; l < DEPTH; ++l) {
        lstm_gemm<<<dim3(N4H / 128, B_ / 128), 256, SMEM_G>>>(
            l, b + (size_t)l * N4H, sc + (size_t)l * BH,
            out_h + (size_t)l * BH, out_c + (size_t)l * BH,
            (l == DEPTH - 1) ? out_final : nullptr);
    }
}

// round 10
// speedup vs baseline: 1.4549x; 1.0023x over previous
#include <cuda_runtime.h>
#include <cuda_fp16.h>
#include <cstdint>

#define DEPTH 4
#define B_    4096
#define H_    1024
#define K_    2048
#define N4H   4096

// ---------------- device scratch ----------------
__device__ __half g_A[DEPTH][B_][K_];    // [prev_out | s_h] fp16
__device__ __half g_W[DEPTH][K_][N4H];   // gate-interleaved: col 4j+g = orig g*1024+j
__device__ int    g_ticket;
__device__ int    g_ready[DEPTH][32];    // finished n-tiles per (layer, m-block)

// ---------------- helpers ----------------
__device__ __forceinline__ uint32_t smem_u32(const void* p) {
    uint32_t a;
    asm("{ .reg .u64 t; cvta.to.shared.u64 t, %1; cvt.u32.u64 %0, t; }" : "=r"(a) : "l"(p));
    return a;
}
__device__ __forceinline__ void cp16(uint32_t dst, const void* src) {
    asm volatile("cp.async.cg.shared.global [%0], [%1], 16;"
                 :: "r"(dst), "l"(__cvta_generic_to_global(src)));
}
__device__ __forceinline__ void ldsm4(uint32_t* r, uint32_t addr) {
    asm volatile("ldmatrix.sync.aligned.m8n8.x4.shared.b16 {%0,%1,%2,%3}, [%4];"
                 : "=r"(r[0]), "=r"(r[1]), "=r"(r[2]), "=r"(r[3]) : "r"(addr));
}
__device__ __forceinline__ void ldsm4t(uint32_t* r, uint32_t addr) {
    asm volatile("ldmatrix.sync.aligned.m8n8.x4.trans.shared.b16 {%0,%1,%2,%3}, [%4];"
                 : "=r"(r[0]), "=r"(r[1]), "=r"(r[2]), "=r"(r[3]) : "r"(addr));
}
__device__ __forceinline__ void mma16816(float* c, const uint32_t* a, const uint32_t* b) {
    asm volatile("mma.sync.aligned.m16n8k16.row.col.f32.f16.f16.f32 "
                 "{%0,%1,%2,%3}, {%4,%5,%6,%7}, {%8,%9}, {%0,%1,%2,%3};"
                 : "+f"(c[0]), "+f"(c[1]), "+f"(c[2]), "+f"(c[3])
                 : "r"(a[0]), "r"(a[1]), "r"(a[2]), "r"(a[3]), "r"(b[0]), "r"(b[1]));
}
__device__ __forceinline__ float sigm(float x) { return 1.0f / (1.0f + __expf(-x)); }

// ---------------- prologue kernels ----------------
__global__ void init_counters() {
    if (threadIdx.x == 0) g_ticket = 0;
    if (threadIdx.x < DEPTH * 32) ((int*)g_ready)[threadIdx.x] = 0;
}
// W'[l][k][4j+g] = W[l][k][g*1024+j], fp16  (mapping verified: rel_err identical)
__global__ void cvt_w(const float* __restrict__ W) {
    size_t i = (size_t)blockIdx.x * blockDim.x + threadIdx.x;
    size_t l = i >> 21;
    size_t rem = i & ((1u << 21) - 1);
    size_t k = rem >> 10, j = rem & 1023;
    const float* src = W + (l * K_ + k) * N4H;
    float vi = src[j], vf = src[1024 + j], vo = src[2048 + j], vg = src[3072 + j];
    __half2* dst = (__half2*)&g_W[l][k][4 * j];
    dst[0] = __floats2half2_rn(vi, vf);
    dst[1] = __floats2half2_rn(vo, vg);
}
__global__ void pack_sh(const float* __restrict__ sh) {
    size_t i = (size_t)blockIdx.x * blockDim.x + threadIdx.x;
    size_t e = i * 4;
    size_t l = e / ((size_t)B_ * H_);
    size_t r = e % ((size_t)B_ * H_);
    size_t m = r >> 10, j = r & 1023;
    float4 v = ((const float4*)sh)[i];
    __half2* dst = (__half2*)&g_A[l][m][H_ + j];
    dst[0] = __floats2half2_rn(v.x, v.y);
    dst[1] = __floats2half2_rn(v.z, v.w);
}
__global__ void pack_x(const float* __restrict__ x) {
    size_t i = (size_t)blockIdx.x * blockDim.x + threadIdx.x;
    size_t e = i * 4;
    size_t m = e >> 10, j = e & 1023;
    float4 v = ((const float4*)x)[i];
    __half2* dst = (__half2*)&g_A[0][m][j];
    dst[0] = __floats2half2_rn(v.x, v.y);
    dst[1] = __floats2half2_rn(v.z, v.w);
}

// ---------------- persistent fused GEMM + LSTM ----------------
// BM=128, BN=128, BK=32, 5 stages, 1 sync per 2 iters, 256 thr (8 warps 2m x 4n),
// warp tile 64x32, 2 CTAs/SM. 4096 tiles via dynamic ticket; cross-layer deps
// via g_ready counters (producer tickets are exactly 1024 earlier).
#define BK      32
#define ASTRIDE 80
#define BSTRIDE 272
#define A_STG   (128 * ASTRIDE)    // 10240
#define B_STG   (BK * BSTRIDE)     // 8704
#define STG     (A_STG + B_STG)    // 18944
#define NSTAGE  5
#define CIN_STRIDE 144
#define CIN_BYTES  (128 * CIN_STRIDE)          // 18432
#define SMEM_G  (NSTAGE * STG + CIN_BYTES)     // 113152
#define NTILES  (DEPTH * 32 * 32)              // 4096
#define GRID_P  296

__device__ __forceinline__ void process_tile(
    int layer, int m0, int n0, char* smem,
    const float* __restrict__ bias_all, const float* __restrict__ sc_all,
    float* __restrict__ out_h, float* __restrict__ out_c,
    float* __restrict__ out_final)
{
    const uint32_t sbase = smem_u32(smem);
    const uint32_t scin  = sbase + NSTAGE * STG;

    const int tid = threadIdx.x;
    const int wid = tid >> 5, lane = tid & 31;
    const int jbase = n0 >> 2;
    const int wm = (wid >> 2) * 64, wn = (wid & 3) * 32;

    const float* bias = bias_all + (size_t)layer * N4H;
    const float* c_in = sc_all + (size_t)layer * B_ * H_;
    float* h_out = out_h + (size_t)layer * B_ * H_;
    float* c_out = out_c + (size_t)layer * B_ * H_;
    float* final_out = (layer == DEPTH - 1) ? out_final : nullptr;

    const __half* Ag = &g_A[layer][0][0];
    const __half* Wg = &g_W[layer][0][0];
    __half* a_next = (layer + 1 < DEPTH) ? &g_A[layer + 1][0][0] : nullptr;

    const int ar = tid >> 1, ac = (tid & 1) * 2;
    const int br = tid >> 4, bc = tid & 15;

    auto load_stage = [&](int s, int k0) {
        uint32_t da = sbase + s * STG;
        uint32_t db = da + A_STG;
        cp16(da + ar * ASTRIDE + ac * 16,       Ag + (size_t)(m0 + ar) * K_ + k0 + ac * 8);
        cp16(da + ar * ASTRIDE + (ac + 1) * 16, Ag + (size_t)(m0 + ar) * K_ + k0 + (ac + 1) * 8);
        cp16(db + br * BSTRIDE + bc * 16,        Wg + (size_t)(k0 + br) * N4H + n0 + bc * 8);
        cp16(db + (br + 16) * BSTRIDE + bc * 16, Wg + (size_t)(k0 + br + 16) * N4H + n0 + bc * 8);
        asm volatile("cp.async.commit_group;" ::: "memory");
    };

    float acc[4][4][4];
    #pragma unroll
    for (int i = 0; i < 4; ++i)
        #pragma unroll
        for (int j = 0; j < 4; ++j)
            #pragma unroll
            for (int q = 0; q < 4; ++q) acc[i][j][q] = 0.f;

    // c_in prefetch (oldest group)
    #pragma unroll
    for (int it = 0; it < 4; ++it) {
        int idx = tid + 256 * it;
        int r = idx >> 3, ch = idx & 7;
        cp16(scin + r * CIN_STRIDE + ch * 16,
             c_in + (size_t)(m0 + r) * H_ + jbase + ch * 4);
    }
    asm volatile("cp.async.commit_group;" ::: "memory");

    load_stage(0, 0);
    load_stage(1, BK);
    load_stage(2, 2 * BK);

    // hoisted per-thread fragment offsets
    uint32_t aoff[4], boff[2];
    #pragma unroll
    for (int mf = 0; mf < 4; ++mf)
        aoff[mf] = (wm + mf * 16 + (lane & 15)) * ASTRIDE + (lane >> 4) * 16;
    #pragma unroll
    for (int ns = 0; ns < 2; ++ns)
        boff[ns] = (lane & 15) * BSTRIDE + (wn + ns * 16 + (lane >> 4) * 8) * 2;

    auto subiter = [&](int st, int pf_slot, int pf_k0, bool do_pf) {
        const uint32_t da = sbase + st * STG;
        const uint32_t db = da + A_STG;
        uint32_t af[4][4], bf[2][4];
        #pragma unroll
        for (int mf = 0; mf < 4; ++mf) ldsm4(af[mf], da + aoff[mf]);
        #pragma unroll
        for (int ns = 0; ns < 2; ++ns) ldsm4t(bf[ns], db + boff[ns]);
        if (do_pf) load_stage(pf_slot, pf_k0);
        #pragma unroll
        for (int mf = 0; mf < 4; ++mf)
            #pragma unroll
            for (int nf = 0; nf < 4; ++nf)
                mma16816(acc[mf][nf], af[mf], &bf[nf >> 1][(nf & 1) * 2]);
        #pragma unroll
        for (int mf = 0; mf < 4; ++mf) ldsm4(af[mf], da + aoff[mf] + 32);
        #pragma unroll
        for (int ns = 0; ns < 2; ++ns) ldsm4t(bf[ns], db + boff[ns] + 16 * BSTRIDE);
        #pragma unroll
        for (int mf = 0; mf < 4; ++mf)
            #pragma unroll
            for (int nf = 0; nf < 4; ++nf)
                mma16816(acc[mf][nf], af[mf], &bf[nf >> 1][(nf & 1) * 2]);
    };

    const int NIT = K_ / BK;  // 64
    #pragma unroll 1
    for (int kt = 0; kt < NIT; kt += 2) {
        if (kt + 2 < NIT) asm volatile("cp.async.wait_group 1;" ::: "memory");
        else              asm volatile("cp.async.wait_group 0;" ::: "memory");
        __syncthreads();
        subiter(kt % NSTAGE,       (kt + 3) % NSTAGE, (kt + 3) * BK, kt + 3 < NIT);
        subiter((kt + 1) % NSTAGE, (kt + 4) % NSTAGE, (kt + 4) * BK, kt + 4 < NIT);
    }
    __syncthreads();   // pipeline smem free; reuse for h/c staging

    // -------- LSTM epilogue (mapping verified) --------
    float* sh_h = (float*)smem;                     // [128][33]
    float* sh_c = sh_h + 128 * 33;                  // [128][33]
    const float* sh_cin = (const float*)(smem + (NSTAGE * STG));

    const int q = lane & 3;
    const bool has_if = (q & 1) == 0;
    const int rloc = wm + (lane >> 2);

    float bi[4], bfs[4], bo[4], bg[4];
    int jloc[4];
    #pragma unroll
    for (int nf = 0; nf < 4; ++nf) {
        int jl = (wn >> 2) + nf * 2 + (q >> 1);
        jloc[nf] = jl;
        int j = jbase + jl;
        bi[nf]  = bias[j];
        bfs[nf] = bias[1024 + j];
        bo[nf]  = bias[2048 + j];
        bg[nf]  = bias[3072 + j];
    }

    #pragma unroll
    for (int mf = 0; mf < 4; ++mf) {
        #pragma unroll
        for (int nf = 0; nf < 4; ++nf) {
            float v0 = acc[mf][nf][0], v1 = acc[mf][nf][1];
            float v2 = acc[mf][nf][2], v3 = acc[mf][nf][3];
            float p0 = __shfl_xor_sync(0xffffffffu, v0, 1);
            float p1 = __shfl_xor_sync(0xffffffffu, v1, 1);
            float p2 = __shfl_xor_sync(0xffffffffu, v2, 1);
            float p3 = __shfl_xor_sync(0xffffffffu, v3, 1);
            float zi, zf, zo, zg;
            int ml;
            if (has_if) { zi = v0; zf = v1; zo = p0; zg = p1; ml = rloc + mf * 16; }
            else        { zi = p2; zf = p3; zo = v2; zg = v3; ml = rloc + mf * 16 + 8; }
            const int jl = jloc[nf];
            float ig = sigm(zi + bi[nf]);
            float fg = sigm(zf + bfs[nf]);
            float og = sigm(zo + bo[nf]);
            float gg = tanhf(zg + bg[nf]);
            float cn = sh_cin[ml * 36 + jl] * fg + gg * ig;
            float hn = tanhf(cn) * og;
            sh_h[ml * 33 + jl] = hn;
            sh_c[ml * 33 + jl] = cn;
        }
    }
    __syncthreads();

    // -------- coalesced output pass --------
    #pragma unroll
    for (int it = 0; it < 16; ++it) {
        int idx = tid + 256 * it;
        int r = idx >> 5, c2 = idx & 31;
        float hv = sh_h[r * 33 + c2];
        float cv = sh_c[r * 33 + c2];
        const size_t off = (size_t)(m0 + r) * H_ + jbase + c2;
        h_out[off] = hv;
        c_out[off] = cv;
        if (final_out) final_out[off] = hv;
        if (a_next) a_next[(size_t)(m0 + r) * K_ + jbase + c2] = __float2half(hv);
    }
    __syncthreads();   // outputs read from smem done before next tile overwrites
}

__global__ void __launch_bounds__(256, 2)
lstm_all(const float* __restrict__ bias_all, const float* __restrict__ sc_all,
         float* __restrict__ out_h, float* __restrict__ out_c,
         float* __restrict__ out_final) {
    extern __shared__ __align__(16) char smem[];
    __shared__ int s_t;
    const int tid = threadIdx.x;

    for (;;) {
        if (tid == 0) s_t = atomicAdd(&g_ticket, 1);
        __syncthreads();
        const int t = s_t;
        if (t >= NTILES) return;
        const int layer = t >> 10;
        const int mb = (t >> 5) & 31;
        const int nb = t & 31;

        if (layer > 0) {
            if (tid == 0) {
                const int* cp = &g_ready[layer - 1][mb];
                int v;
                for (;;) {
                    asm volatile("ld.global.acquire.gpu.b32 %0, [%1];"
                                 : "=r"(v) : "l"(cp) : "memory");
                    if (v >= 32) break;
                    __nanosleep(128);
                }
            }
            __syncthreads();
        }

        process_tile(layer, mb * 128, nb * 128, smem,
                     bias_all, sc_all, out_h, out_c, out_final);

        __threadfence();
        __syncthreads();
        if (tid == 0) atomicAdd(&g_ready[layer][mb], 1);
    }
}

// ---------------- launch ----------------
extern "C" void kernel_launch(void* const* d_in, const int* in_sizes, int n_in,
                              void* d_out, int out_size) {
    const float* x  = (const float*)d_in[0];
    const float* sh = (const float*)d_in[1];
    const float* sc = (const float*)d_in[2];
    const float* W  = (const float*)d_in[3];
    const float* b  = (const float*)d_in[4];
    float* out = (float*)d_out;

    const size_t BH = (size_t)B_ * H_;
    float* out_final = out;
    float* out_h     = out + BH;
    float* out_c     = out + BH + DEPTH * BH;

    cudaFuncSetAttribute(lstm_all, cudaFuncAttributeMaxDynamicSharedMemorySize, SMEM_G);

    init_counters<<<1, 256>>>();
    cvt_w<<<(DEPTH * (size_t)K_ * 1024) / 256, 256>>>(W);
    pack_sh<<<(DEPTH * BH / 4) / 256, 256>>>(sh);
    pack_x<<<(BH / 4) / 256, 256>>>(x);

    lstm_all<<<GRID_P, 256, SMEM_G>>>(b, sc, out_h, out_c, out_final);
}